// round 12
// baseline (speedup 1.0000x reference)
#include <cuda_runtime.h>
#include <cuda_bf16.h>
#include <cstdint>

// ComboSumModule: 6 tensors (N=2048, M_i, K_i) fp32, sum over axis 1.
//   x0:(2048,128,64) x1:(2048,32,32) x2:(2048,64,64)
//   x3:(2048,16,48)  x4:(2048,200,32) x5:(2048,8,8)
// Output float offsets: 0, 131072, 196608, 327680, 425984, 491520.
//
// R11: long sequential streams per warp (16KB vs 4KB) to raise DRAM row-hit
// rate. NW=2 for seg0/seg4 (2-warp smem combine), NW=1 elsewhere in warp
// form. Single launch, no atomics. Heavy blocks first.

__device__ __forceinline__ void f4_acc(float4& a, const float4 v) {
    a.x += v.x; a.y += v.y; a.z += v.z; a.w += v.w;
}

// F4N: float4 per n. Kv: K/4. NPB: n per block. NW: warps per n (NPB*NW==8).
// CF4 = F4N/NW float4 per warp-chunk. FITERS = CF4/32 (exact).
template<int F4N, int Kv, int NPB, int NW, int FITERS>
__device__ __forceinline__ void seg_block(const float* __restrict__ in,
                                          float* __restrict__ out,
                                          int blk, int tid,
                                          float4 (*part)[16]) {
    const float4* __restrict__ in4 = reinterpret_cast<const float4*>(in);
    float4* __restrict__ out4 = reinterpret_cast<float4*>(out);
    constexpr int CF4 = F4N / NW;
    const int w    = tid >> 5;
    const int lane = tid & 31;
    const int n_l  = w / NW;
    const int c    = w % NW;
    const int n    = blk * NPB + n_l;

    const float4* __restrict__ p = in4 + (size_t)n * F4N + c * CF4 + lane;

    float4 a0 = make_float4(0.f, 0.f, 0.f, 0.f);
    float4 a1 = make_float4(0.f, 0.f, 0.f, 0.f);
    #pragma unroll 8
    for (int i = 0; i < FITERS; ++i) {
        float4 v = __ldcs(p + i * 32);          // warp: 512B contiguous
        if (i & 1) f4_acc(a1, v); else f4_acc(a0, v);
    }
    float4 s;
    s.x = a0.x + a1.x; s.y = a0.y + a1.y;
    s.z = a0.z + a1.z; s.w = a0.w + a1.w;

    // In-warp: fold the 32/Kv row-phases (lanes equal mod Kv).
    #pragma unroll
    for (int d = Kv; d < 32; d <<= 1) {
        s.x += __shfl_xor_sync(0xFFFFFFFFu, s.x, d);
        s.y += __shfl_xor_sync(0xFFFFFFFFu, s.y, d);
        s.z += __shfl_xor_sync(0xFFFFFFFFu, s.z, d);
        s.w += __shfl_xor_sync(0xFFFFFFFFu, s.w, d);
    }

    if (NW == 1) {
        if (lane < Kv) out4[(size_t)n * Kv + lane] = s;
    } else {
        if (lane < Kv) part[w][lane] = s;
        __syncthreads();
        if (tid < NPB * Kv) {                   // NPB*Kv <= 64
            const int nl = tid / Kv;
            const int k  = tid % Kv;
            float4 t = part[nl * NW][k];
            #pragma unroll
            for (int ww = 1; ww < NW; ++ww)
                f4_acc(t, part[nl * NW + ww][k]);
            out4[(size_t)(blk * NPB + nl) * Kv + k] = t;
        }
    }
}

// Per-thread style for Kv not dividing 32 / tiny segments.
template<int M, int Kv, int C>
__device__ __forceinline__ void seg_thread(const float* __restrict__ in,
                                           float* __restrict__ out, int t) {
    const float4* __restrict__ in4 = reinterpret_cast<const float4*>(in);
    float4* __restrict__ out4 = reinterpret_cast<float4*>(out);
    const int k = t % Kv;
    const int n = t / Kv;
    const float4* __restrict__ p = in4 + (size_t)n * (size_t)(M * Kv) + k;
    float4 a0 = make_float4(0.f, 0.f, 0.f, 0.f);
    float4 a1 = make_float4(0.f, 0.f, 0.f, 0.f);
    #pragma unroll
    for (int m = 0; m < C; ++m) {
        float4 v = __ldcs(p + (size_t)m * Kv);
        if (m & 1) f4_acc(a1, v); else f4_acc(a0, v);
    }
    float4 s;
    s.x = a0.x + a1.x; s.y = a0.y + a1.y;
    s.z = a0.z + a1.z; s.w = a0.w + a1.w;
    out4[(size_t)n * Kv + k] = s;
}

// Block layout (heavy first):
//  seg0: [0, 512)       NPB=4 NW=2 CF4=1024 FITERS=32  (16KB streams, 128KB/blk)
//  seg2: [512, 768)     NPB=8 NW=1 CF4=1024 FITERS=32  (16KB streams, 128KB/blk)
//  seg4: [768, 1280)    NPB=4 NW=2 CF4=800  FITERS=25  (12.8KB streams, 102KB/blk)
//  seg3: [1280, 1376)   thread-style (64KB/blk)
//  seg1: [1376, 1632)   NPB=8 NW=1 CF4=256  FITERS=8   (4KB streams, 32KB/blk)
//  seg5: [1632, 1648)   thread-style
static constexpr int TOTAL_BLOCKS = 1648;

__global__ __launch_bounds__(256, 7)
void combo_sum_kernel(const float* __restrict__ x0, const float* __restrict__ x1,
                      const float* __restrict__ x2, const float* __restrict__ x3,
                      const float* __restrict__ x4, const float* __restrict__ x5,
                      float* __restrict__ out) {
    __shared__ float4 part[8][16];
    const int blk = blockIdx.x;
    const int tid = threadIdx.x;

    if (blk < 512) {
        seg_block<2048, 16, 4, 2, 32>(x0, out + 0,      blk,        tid, part);
    } else if (blk < 768) {
        seg_block<1024, 16, 8, 1, 32>(x2, out + 196608, blk - 512,  tid, part);
    } else if (blk < 1280) {
        seg_block<1600, 8,  4, 2, 25>(x4, out + 425984, blk - 768,  tid, part);
    } else if (blk < 1376) {
        seg_thread<16, 12, 16>(x3, out + 327680, (blk - 1280) * 256 + tid);
    } else if (blk < 1632) {
        seg_block<256,  8,  8, 1, 8 >(x1, out + 131072, blk - 1376, tid, part);
    } else {
        seg_thread<8, 2, 8>(x5, out + 491520, (blk - 1632) * 256 + tid);
    }
}

extern "C" void kernel_launch(void* const* d_in, const int* in_sizes, int n_in,
                              void* d_out, int out_size) {
    const float* x0 = (const float*)d_in[0];
    const float* x1 = (const float*)d_in[1];
    const float* x2 = (const float*)d_in[2];
    const float* x3 = (const float*)d_in[3];
    const float* x4 = (const float*)d_in[4];
    const float* x5 = (const float*)d_in[5];
    float* out = (float*)d_out;

    combo_sum_kernel<<<TOTAL_BLOCKS, 256>>>(x0, x1, x2, x3, x4, x5, out);
}